// round 2
// baseline (speedup 1.0000x reference)
#include <cuda_runtime.h>

#define BATCH 2
#define CH    512
#define TIME  2048
#define DIM   64
#define TT    16
#define EPS_F 1e-6f

// Intermediate attention output [B, C, T] (scratch — no allocs allowed)
__device__ float g_attn[BATCH * CH * TIME];

__device__ __forceinline__ float elu1(float u) {
    // elu(u)+1 = exp(min(u,0)) + max(u,0)   (exact at u=0: 1)
    return __expf(fminf(u, 0.f)) + fmaxf(u, 0.f);
}

// ---------------------------------------------------------------------------
// Kernel A: linear attention over channels, per (b, 16-wide t tile)
// ---------------------------------------------------------------------------
__global__ __launch_bounds__(512) void attn_kernel(
    const float* __restrict__ x,
    const float* __restrict__ wq, const float* __restrict__ bq,
    const float* __restrict__ wk, const float* __restrict__ bk,
    const float* __restrict__ wv, const float* __restrict__ bv)
{
    __shared__ float  xs[CH][TT];        // 32 KB
    __shared__ float2 sSZ[DIM][TT];      // 8 KB   (S, clamped Z)
    __shared__ float2 swb[DIM];          // wq,bq packed

    const int tile = blockIdx.x;
    const int b    = tile / (TIME / TT);
    const int t0   = (tile % (TIME / TT)) * TT;
    const int tid  = threadIdx.x;

    if (tid < DIM) swb[tid] = make_float2(wq[tid], bq[tid]);

    // Load x[b, :, t0:t0+16] as float4 rows
    const float* xg = x + (size_t)b * CH * TIME + t0;
    for (int i = tid; i < CH * (TT / 4); i += 512) {
        int c = i / (TT / 4);
        int j = i % (TT / 4);
        float4 v = *reinterpret_cast<const float4*>(&xg[(size_t)c * TIME + j * 4]);
        xs[c][j * 4 + 0] = v.x; xs[c][j * 4 + 1] = v.y;
        xs[c][j * 4 + 2] = v.z; xs[c][j * 4 + 3] = v.w;
    }
    __syncthreads();

    const float wvv = __ldg(wv);
    const float bvv = __ldg(bv);

    // Phase 1: S[d,t] = sum_c phi_k * v ;  Z[d,t] = sum_c phi_k
    // v = x*wv + bv  =>  S = wv * sum(phi*x) + bv * Z
    for (int p = tid; p < DIM * TT; p += 512) {
        const int d = p / TT, t = p % TT;
        const float wkd = wk[d], bkd = bk[d];
        float SX = 0.f, Z = 0.f;
        #pragma unroll 8
        for (int c = 0; c < CH; c++) {
            float xv  = xs[c][t];
            float phi = elu1(fmaf(xv, wkd, bkd));
            SX = fmaf(phi, xv, SX);
            Z += phi;
        }
        float S = fmaf(wvv, SX, bvv * Z);
        sSZ[d][t] = make_float2(S, fmaxf(Z, EPS_F));
    }
    __syncthreads();

    // Phase 2: out[c,t] = (sum_d phi_q*S_d) / (sum_d phi_q*Z_d)
    float* outp = g_attn + (size_t)b * CH * TIME + t0;
    for (int p = tid; p < CH * TT; p += 512) {
        const int c = p / TT, t = p % TT;
        const float xv = xs[c][t];
        float num = 0.f, den = 0.f;
        #pragma unroll 8
        for (int d = 0; d < DIM; d++) {
            float2 wb  = swb[d];
            float  phi = elu1(fmaf(xv, wb.x, wb.y));
            float2 sz  = sSZ[d][t];
            num = fmaf(phi, sz.x, num);
            den = fmaf(phi, sz.y, den);
        }
        outp[(size_t)c * TIME + t] = num / den;
    }
}

// ---------------------------------------------------------------------------
// Kernel B: out[b,o,t] = x[b,o,t] + b_proj[o] + sum_c W[o,c] * attn[b,c,t]
// Classic 128x128x16 register-blocked SGEMM, 256 threads, 8x8 micro-tile.
// ---------------------------------------------------------------------------
#define BM 128
#define BN 128
#define BK 16

__global__ __launch_bounds__(256) void proj_kernel(
    const float* __restrict__ W, const float* __restrict__ bp,
    const float* __restrict__ x, float* __restrict__ out)
{
    __shared__ float As[BK][BM];   // W^T tile
    __shared__ float Bs[BK][BN];   // attn tile

    const int b   = blockIdx.z;
    const int m0  = blockIdx.y * BM;
    const int n0  = blockIdx.x * BN;
    const int tid = threadIdx.x;
    const int tm  = (tid / 16) * 8;
    const int tn  = (tid % 16) * 8;

    const float* Ab = g_attn + (size_t)b * CH * TIME;

    float acc[8][8] = {};

    for (int k0 = 0; k0 < CH; k0 += BK) {
        // W tile: rows m0..m0+127, cols k0..k0+15 -> As[k][m]
        #pragma unroll
        for (int i = 0; i < 2; i++) {
            int id = tid + i * 256;              // 0..511
            int r  = id >> 2;                    // row 0..127
            int c4 = (id & 3) * 4;               // 0,4,8,12
            float4 v = *reinterpret_cast<const float4*>(&W[(size_t)(m0 + r) * CH + k0 + c4]);
            As[c4 + 0][r] = v.x; As[c4 + 1][r] = v.y;
            As[c4 + 2][r] = v.z; As[c4 + 3][r] = v.w;
        }
        // attn tile: rows k0..k0+15, cols n0..n0+127 -> Bs[k][n]
        #pragma unroll
        for (int i = 0; i < 2; i++) {
            int id = tid + i * 256;
            int r  = id >> 5;                    // 0..15
            int cc = (id & 31) * 4;              // 0..124
            float4 v = *reinterpret_cast<const float4*>(&Ab[(size_t)(k0 + r) * TIME + n0 + cc]);
            *reinterpret_cast<float4*>(&Bs[r][cc]) = v;
        }
        __syncthreads();

        #pragma unroll
        for (int k = 0; k < BK; k++) {
            float a[8], bb[8];
            *reinterpret_cast<float4*>(&a[0])  = *reinterpret_cast<float4*>(&As[k][tm]);
            *reinterpret_cast<float4*>(&a[4])  = *reinterpret_cast<float4*>(&As[k][tm + 4]);
            *reinterpret_cast<float4*>(&bb[0]) = *reinterpret_cast<float4*>(&Bs[k][tn]);
            *reinterpret_cast<float4*>(&bb[4]) = *reinterpret_cast<float4*>(&Bs[k][tn + 4]);
            #pragma unroll
            for (int i = 0; i < 8; i++)
                #pragma unroll
                for (int j = 0; j < 8; j++)
                    acc[i][j] = fmaf(a[i], bb[j], acc[i][j]);
        }
        __syncthreads();
    }

    // Epilogue: bias + residual
    const float* xb = x + (size_t)b * CH * TIME;
    float*       ob = out + (size_t)b * CH * TIME;
    #pragma unroll
    for (int i = 0; i < 8; i++) {
        int m = m0 + tm + i;
        float bias = bp[m];
        #pragma unroll
        for (int j = 0; j < 8; j += 4) {
            const size_t off = (size_t)m * TIME + n0 + tn + j;
            float4 xv = *reinterpret_cast<const float4*>(&xb[off]);
            float4 o;
            o.x = xv.x + bias + acc[i][j + 0];
            o.y = xv.y + bias + acc[i][j + 1];
            o.z = xv.z + bias + acc[i][j + 2];
            o.w = xv.w + bias + acc[i][j + 3];
            *reinterpret_cast<float4*>(&ob[off]) = o;
        }
    }
}

// ---------------------------------------------------------------------------
extern "C" void kernel_launch(void* const* d_in, const int* in_sizes, int n_in,
                              void* d_out, int out_size) {
    const float* x  = (const float*)d_in[0];
    const float* wq = (const float*)d_in[1];
    const float* bq = (const float*)d_in[2];
    const float* wk = (const float*)d_in[3];
    const float* bk = (const float*)d_in[4];
    const float* wv = (const float*)d_in[5];
    const float* bv = (const float*)d_in[6];
    const float* wp = (const float*)d_in[7];
    const float* bp = (const float*)d_in[8];
    float* out = (float*)d_out;

    attn_kernel<<<BATCH * (TIME / TT), 512>>>(x, wq, bq, wk, bk, wv, bv);

    dim3 grid(TIME / BN, CH / BM, BATCH);
    proj_kernel<<<grid, 256>>>(wp, bp, x, out);
}

// round 3
// speedup vs baseline: 1.2677x; 1.2677x over previous
#include <cuda_runtime.h>
#include <cstdint>

#define BATCH 2
#define CH    512
#define TIME  2048
#define DIM   64
#define TT    8
#define EPS_F 1e-6f
#define L2E_F 1.44269504088896340736f
#define LN2_F 0.69314718055994530942f

// Intermediate attention output [B, C, T] (scratch — no allocs allowed)
__device__ float g_attn[BATCH * CH * TIME];

__device__ __forceinline__ float ex2f(float v) {
    float r;
    asm("ex2.approx.f32 %0, %1;" : "=f"(r) : "f"(v));
    return r;
}

// ---------------------------------------------------------------------------
// Kernel A: linear attention over channels.
// One warp per t (TT=8 warps / block). All x reads are warp-broadcast LDS.
// phi(u) = elu(u)+1 = exp(min(u,0)) + max(u,0)
//        = ex2(min(u2,0)) + ln2*max(u2,0),  u2 = x*(w*log2e) + (b*log2e)
// ---------------------------------------------------------------------------
__global__ __launch_bounds__(256) void attn_kernel(
    const float* __restrict__ x,
    const float* __restrict__ wq, const float* __restrict__ bq,
    const float* __restrict__ wk, const float* __restrict__ bk,
    const float* __restrict__ wv, const float* __restrict__ bv)
{
    __shared__ float  xs[TT][CH];     // 16 KB, t-major for broadcast reads
    __shared__ float2 sz[TT][DIM];    // 4 KB  (S, clamped Z)
    __shared__ float2 wbq[DIM];       // pre-scaled (wq*log2e, bq*log2e)

    const int tile = blockIdx.x;                 // 512 tiles
    const int b    = tile / (TIME / TT);
    const int t0   = (tile % (TIME / TT)) * TT;
    const int tid  = threadIdx.x;
    const int wid  = tid >> 5;
    const int lane = tid & 31;

    if (tid < DIM) wbq[tid] = make_float2(wq[tid] * L2E_F, bq[tid] * L2E_F);

    // Load x[b, :, t0:t0+8] -> xs[t][c]  (coalesced float4 along t)
    const float* xg = x + (size_t)b * CH * TIME + t0;
    for (int i = tid; i < CH * (TT / 4); i += 256) {
        int c = i >> 1;
        int j = (i & 1) * 4;
        float4 v = *reinterpret_cast<const float4*>(&xg[(size_t)c * TIME + j]);
        xs[j + 0][c] = v.x; xs[j + 1][c] = v.y;
        xs[j + 2][c] = v.z; xs[j + 3][c] = v.w;
    }
    __syncthreads();

    const int t = wid;

    // ---- Phase 1: per (d,t): S = wv*sum(phi_k*x) + bv*Z ; Z = sum(phi_k) ----
    {
        const int d0 = lane, d1 = lane + 32;
        const float w20 = wk[d0] * L2E_F, b20 = bk[d0] * L2E_F;
        const float w21 = wk[d1] * L2E_F, b21 = bk[d1] * L2E_F;
        float SX0 = 0.f, Z0 = 0.f, SX1 = 0.f, Z1 = 0.f;
        const float* xrow = xs[t];
        #pragma unroll 4
        for (int c = 0; c < CH; c += 4) {
            float4 xv4 = *reinterpret_cast<const float4*>(&xrow[c]);  // broadcast
            float xa[4] = {xv4.x, xv4.y, xv4.z, xv4.w};
            #pragma unroll
            for (int r = 0; r < 4; r++) {
                float xv = xa[r];
                float u0 = fmaf(xv, w20, b20);
                float u1 = fmaf(xv, w21, b21);
                float e0 = ex2f(fminf(u0, 0.f));
                float e1 = ex2f(fminf(u1, 0.f));
                float p0 = fmaf(fmaxf(u0, 0.f), LN2_F, e0);
                float p1 = fmaf(fmaxf(u1, 0.f), LN2_F, e1);
                SX0 = fmaf(p0, xv, SX0); Z0 += p0;
                SX1 = fmaf(p1, xv, SX1); Z1 += p1;
            }
        }
        const float wvv = __ldg(wv), bvv = __ldg(bv);
        sz[t][d0] = make_float2(fmaf(wvv, SX0, bvv * Z0), fmaxf(Z0, EPS_F));
        sz[t][d1] = make_float2(fmaf(wvv, SX1, bvv * Z1), fmaxf(Z1, EPS_F));
    }
    __syncwarp();

    // ---- Phase 2: out[c,t] = sum_d(phi_q*S_d) / sum_d(phi_q*Z_d) ----
    {
        float xr[16], num[16], den[16];
        #pragma unroll
        for (int j = 0; j < 16; j++) {
            xr[j] = xs[t][lane + 32 * j];
            num[j] = 0.f; den[j] = 0.f;
        }
        #pragma unroll 2
        for (int d = 0; d < DIM; d += 2) {
            float4 wb  = *reinterpret_cast<const float4*>(&wbq[d]);    // broadcast
            float4 szp = *reinterpret_cast<const float4*>(&sz[t][d]);  // broadcast
            #pragma unroll
            for (int j = 0; j < 16; j++) {
                float xv = xr[j];
                float u0 = fmaf(xv, wb.x, wb.y);
                float u1 = fmaf(xv, wb.z, wb.w);
                float e0 = ex2f(fminf(u0, 0.f));
                float e1 = ex2f(fminf(u1, 0.f));
                float p0 = fmaf(fmaxf(u0, 0.f), LN2_F, e0);
                float p1 = fmaf(fmaxf(u1, 0.f), LN2_F, e1);
                num[j] = fmaf(p0, szp.x, num[j]);
                den[j] = fmaf(p0, szp.y, den[j]);
                num[j] = fmaf(p1, szp.z, num[j]);
                den[j] = fmaf(p1, szp.w, den[j]);
            }
        }
        // write results back into own xs row (this thread read these slots)
        #pragma unroll
        for (int j = 0; j < 16; j++)
            xs[t][lane + 32 * j] = num[j] / den[j];
    }
    __syncthreads();

    // Coalesced store: g_attn[b][c][t0..t0+7]
    float* outp = g_attn + (size_t)b * CH * TIME + t0;
    for (int i = tid; i < CH * (TT / 4); i += 256) {
        int c = i >> 1;
        int j = (i & 1) * 4;
        float4 v = make_float4(xs[j][c], xs[j + 1][c], xs[j + 2][c], xs[j + 3][c]);
        *reinterpret_cast<float4*>(&outp[(size_t)c * TIME + j]) = v;
    }
}

// ---------------------------------------------------------------------------
// Kernel B: out[b,o,t] = x[b,o,t] + b_proj[o] + sum_c W[o,c]*attn[b,c,t]
// TF32 mma.sync m16n8k8, 128x128x16 CTA tile (double-buffered),
// 8 warps as 2x4 grid of 64x32 warp tiles.
// ---------------------------------------------------------------------------
#define PBM 128
#define PBN 128
#define PBK 16
#define PPAD 8

__device__ __forceinline__ uint32_t f2tf32(float v) {
    uint32_t r;
    asm("cvt.rna.tf32.f32 %0, %1;" : "=r"(r) : "f"(v));
    return r;
}

__device__ __forceinline__ void mma_tf32(float c[4], const uint32_t a[4], const uint32_t b[2]) {
    asm("mma.sync.aligned.m16n8k8.row.col.f32.tf32.tf32.f32 "
        "{%0,%1,%2,%3}, {%4,%5,%6,%7}, {%8,%9}, {%0,%1,%2,%3};"
        : "+f"(c[0]), "+f"(c[1]), "+f"(c[2]), "+f"(c[3])
        : "r"(a[0]), "r"(a[1]), "r"(a[2]), "r"(a[3]), "r"(b[0]), "r"(b[1]));
}

__global__ __launch_bounds__(256) void proj_kernel(
    const float* __restrict__ W, const float* __restrict__ bp,
    const float* __restrict__ x, float* __restrict__ out)
{
    __shared__ uint32_t As[2][PBK][PBM + PPAD];   // [k][m], tf32 bits
    __shared__ uint32_t Bs[2][PBK][PBN + PPAD];   // [k][n], tf32 bits

    const int b   = blockIdx.z;
    const int m0  = blockIdx.y * PBM;
    const int n0  = blockIdx.x * PBN;
    const int tid = threadIdx.x;
    const int wid  = tid >> 5;
    const int lane = tid & 31;
    const int g  = lane >> 2;      // group id 0..7
    const int tg = lane & 3;       // thread-in-group 0..3
    const int wm = (wid >> 2) * 64;  // warp m offset
    const int wn = (wid & 3) * 32;   // warp n offset

    const float* Ab = g_attn + (size_t)b * CH * TIME;

    float acc[4][4][4];
    #pragma unroll
    for (int i = 0; i < 4; i++)
        #pragma unroll
        for (int j = 0; j < 4; j++)
            #pragma unroll
            for (int r = 0; r < 4; r++) acc[i][j][r] = 0.f;

    // ---- staging ----
    auto stage = [&](int buf, int k0) {
        #pragma unroll
        for (int i = 0; i < 2; i++) {
            int e = tid + i * 256;               // 0..511
            // A: W[m0+row][k0+c4 .. +3] -> As[k][m]
            int row = e >> 2, c4 = (e & 3) * 4;
            float4 v = *reinterpret_cast<const float4*>(&W[(size_t)(m0 + row) * CH + k0 + c4]);
            As[buf][c4 + 0][row] = f2tf32(v.x);
            As[buf][c4 + 1][row] = f2tf32(v.y);
            As[buf][c4 + 2][row] = f2tf32(v.z);
            As[buf][c4 + 3][row] = f2tf32(v.w);
            // B: attn[k0+r][n0+n4 .. +3] -> Bs[k][n]
            int r = e >> 5, n4 = (e & 31) * 4;
            float4 u = *reinterpret_cast<const float4*>(&Ab[(size_t)(k0 + r) * TIME + n0 + n4]);
            uint4 tv;
            tv.x = f2tf32(u.x); tv.y = f2tf32(u.y);
            tv.z = f2tf32(u.z); tv.w = f2tf32(u.w);
            *reinterpret_cast<uint4*>(&Bs[buf][r][n4]) = tv;
        }
    };

    stage(0, 0);
    __syncthreads();

    for (int k0 = 0; k0 < CH; k0 += PBK) {
        const int buf = (k0 / PBK) & 1;
        if (k0 + PBK < CH) stage(buf ^ 1, k0 + PBK);

        #pragma unroll
        for (int kk = 0; kk < PBK; kk += 8) {
            uint32_t a[4][4], bf[4][2];
            #pragma unroll
            for (int fm = 0; fm < 4; fm++) {
                int mr = wm + fm * 16 + g;
                a[fm][0] = As[buf][kk + tg    ][mr];
                a[fm][1] = As[buf][kk + tg    ][mr + 8];
                a[fm][2] = As[buf][kk + tg + 4][mr];
                a[fm][3] = As[buf][kk + tg + 4][mr + 8];
            }
            #pragma unroll
            for (int fn = 0; fn < 4; fn++) {
                int nc = wn + fn * 8 + g;
                bf[fn][0] = Bs[buf][kk + tg    ][nc];
                bf[fn][1] = Bs[buf][kk + tg + 4][nc];
            }
            #pragma unroll
            for (int fm = 0; fm < 4; fm++)
                #pragma unroll
                for (int fn = 0; fn < 4; fn++)
                    mma_tf32(acc[fm][fn], a[fm], bf[fn]);
        }
        __syncthreads();
    }

    // ---- epilogue: bias + residual ----
    const float* xb = x + (size_t)b * CH * TIME;
    float*       ob = out + (size_t)b * CH * TIME;
    #pragma unroll
    for (int fm = 0; fm < 4; fm++) {
        int row0 = m0 + wm + fm * 16 + g;
        float bias0 = bp[row0];
        float bias1 = bp[row0 + 8];
        #pragma unroll
        for (int fn = 0; fn < 4; fn++) {
            int col = n0 + wn + fn * 8 + tg * 2;
            size_t off0 = (size_t)row0 * TIME + col;
            size_t off1 = (size_t)(row0 + 8) * TIME + col;
            float2 x0 = *reinterpret_cast<const float2*>(&xb[off0]);
            float2 x1 = *reinterpret_cast<const float2*>(&xb[off1]);
            float2 o0, o1;
            o0.x = x0.x + bias0 + acc[fm][fn][0];
            o0.y = x0.y + bias0 + acc[fm][fn][1];
            o1.x = x1.x + bias1 + acc[fm][fn][2];
            o1.y = x1.y + bias1 + acc[fm][fn][3];
            *reinterpret_cast<float2*>(&ob[off0]) = o0;
            *reinterpret_cast<float2*>(&ob[off1]) = o1;
        }
    }
}

// ---------------------------------------------------------------------------
extern "C" void kernel_launch(void* const* d_in, const int* in_sizes, int n_in,
                              void* d_out, int out_size) {
    const float* x  = (const float*)d_in[0];
    const float* wq = (const float*)d_in[1];
    const float* bq = (const float*)d_in[2];
    const float* wk = (const float*)d_in[3];
    const float* bk = (const float*)d_in[4];
    const float* wv = (const float*)d_in[5];
    const float* bv = (const float*)d_in[6];
    const float* wp = (const float*)d_in[7];
    const float* bp = (const float*)d_in[8];
    float* out = (float*)d_out;

    attn_kernel<<<BATCH * (TIME / TT), 256>>>(x, wq, bq, wk, bk, wv, bv);

    dim3 grid(TIME / PBN, CH / PBM, BATCH);
    proj_kernel<<<grid, 256>>>(wp, bp, x, out);
}

// round 7
// speedup vs baseline: 1.4249x; 1.1240x over previous
#include <cuda_runtime.h>
#include <cstdint>

#define BATCH 2
#define CH    512
#define TIME  2048
#define DIM   64
#define TT    4
#define EPS_F 1e-6f
#define L2E_F 1.44269504088896340736f
#define LN2_F 0.69314718055994530942f

// Intermediate attention output [B, C, T] (scratch — no allocs allowed)
__device__ float g_attn[BATCH * CH * TIME];

__device__ __forceinline__ float ex2f(float v) {
    float r;
    asm("ex2.approx.f32 %0, %1;" : "=f"(r) : "f"(v));
    return r;
}

// ---------------------------------------------------------------------------
// Kernel A: linear attention over channels. TT=4 t's per block, 256 threads.
// Phase 1: warp w -> t = w>>1, d = (w&1)*32 + lane  (broadcast x reads)
// Phase 2: warp w -> t = w>>1, c-half = (w&1), 8 c's per thread
// phi(u) = elu(u)+1 = ex2(min(u2,0)) + ln2*max(u2,0), u2 = x*(w*l2e)+(b*l2e)
// ---------------------------------------------------------------------------
__global__ __launch_bounds__(256) void attn_kernel(
    const float* __restrict__ x,
    const float* __restrict__ wq, const float* __restrict__ bq,
    const float* __restrict__ wk, const float* __restrict__ bk,
    const float* __restrict__ wv, const float* __restrict__ bv)
{
    __shared__ float  xs[TT][CH];     // 8 KB, t-major (broadcast reads)
    __shared__ float2 sz[TT][DIM];    // 2 KB  (S, clamped Z)
    __shared__ float2 wbq[DIM];       // pre-scaled (wq*log2e, bq*log2e)

    const int tile = blockIdx.x;                 // 1024 tiles
    const int b    = tile / (TIME / TT);
    const int t0   = (tile % (TIME / TT)) * TT;
    const int tid  = threadIdx.x;
    const int wid  = tid >> 5;
    const int lane = tid & 31;

    if (tid < DIM) wbq[tid] = make_float2(wq[tid] * L2E_F, bq[tid] * L2E_F);

    // Load x[b, :, t0:t0+4] -> xs[t][c]
    const float* xg = x + (size_t)b * CH * TIME + t0;
    for (int c = tid; c < CH; c += 256) {
        float4 v = *reinterpret_cast<const float4*>(&xg[(size_t)c * TIME]);
        xs[0][c] = v.x; xs[1][c] = v.y; xs[2][c] = v.z; xs[3][c] = v.w;
    }
    __syncthreads();

    const int t = wid >> 1;

    // ---- Phase 1: per (d,t): S = wv*sum(phi_k*x) + bv*Z ; Z = sum(phi_k) ----
    {
        const int d = (wid & 1) * 32 + lane;
        const float w2 = wk[d] * L2E_F, b2 = bk[d] * L2E_F;
        float SX = 0.f, Z = 0.f;
        const float* xrow = xs[t];
        #pragma unroll 4
        for (int c = 0; c < CH; c += 4) {
            float4 x4 = *reinterpret_cast<const float4*>(&xrow[c]);  // broadcast
            float xa[4] = {x4.x, x4.y, x4.z, x4.w};
            #pragma unroll
            for (int r = 0; r < 4; r++) {
                float xv = xa[r];
                float u = fmaf(xv, w2, b2);
                float e = ex2f(fminf(u, 0.f));
                float p = fmaf(fmaxf(u, 0.f), LN2_F, e);
                SX = fmaf(p, xv, SX);
                Z += p;
            }
        }
        const float wvv = __ldg(wv), bvv = __ldg(bv);
        sz[t][d] = make_float2(fmaf(wvv, SX, bvv * Z), fmaxf(Z, EPS_F));
    }
    __syncthreads();

    // ---- Phase 2: out[c,t] = sum_d(phi_q*S_d) / sum_d(phi_q*Z_d) ----
    {
        const int base = lane + (wid & 1) * 256;
        float xr[8], num[8], den[8];
        #pragma unroll
        for (int j = 0; j < 8; j++) {
            xr[j] = xs[t][base + 32 * j];
            num[j] = 0.f; den[j] = 0.f;
        }
        #pragma unroll 4
        for (int d = 0; d < DIM; d += 2) {
            float4 wb  = *reinterpret_cast<const float4*>(&wbq[d]);    // broadcast
            float4 szp = *reinterpret_cast<const float4*>(&sz[t][d]);  // broadcast
            #pragma unroll
            for (int j = 0; j < 8; j++) {
                float xv = xr[j];
                float u0 = fmaf(xv, wb.x, wb.y);
                float u1 = fmaf(xv, wb.z, wb.w);
                float e0 = ex2f(fminf(u0, 0.f));
                float e1 = ex2f(fminf(u1, 0.f));
                float p0 = fmaf(fmaxf(u0, 0.f), LN2_F, e0);
                float p1 = fmaf(fmaxf(u1, 0.f), LN2_F, e1);
                num[j] = fmaf(p0, szp.x, num[j]);
                den[j] = fmaf(p0, szp.y, den[j]);
                num[j] = fmaf(p1, szp.z, num[j]);
                den[j] = fmaf(p1, szp.w, den[j]);
            }
        }
        #pragma unroll
        for (int j = 0; j < 8; j++)
            xs[t][base + 32 * j] = num[j] / den[j];
    }
    __syncthreads();

    // Coalesced store: g_attn[b][c][t0..t0+3]
    float* outp = g_attn + (size_t)b * CH * TIME + t0;
    for (int c = tid; c < CH; c += 256) {
        float4 v = make_float4(xs[0][c], xs[1][c], xs[2][c], xs[3][c]);
        *reinterpret_cast<float4*>(&outp[(size_t)c * TIME]) = v;
    }
}

// ---------------------------------------------------------------------------
// Kernel B: out[b,o,t] = x[b,o,t] + b_proj[o] + sum_c W[o,c]*attn[b,c,t]
// TF32 mma m16n8k8. 64x64x16 CTA tile double-buffered, 128 threads,
// 4 warps as 2x2 grid of 32x32 warp tiles. 512 CTAs for occupancy.
// ---------------------------------------------------------------------------
#define PBM 64
#define PBN 64
#define PBK 16
#define PPAD 8

__device__ __forceinline__ uint32_t f2tf32(float v) {
    uint32_t r;
    asm("cvt.rna.tf32.f32 %0, %1;" : "=r"(r) : "f"(v));
    return r;
}

__device__ __forceinline__ void mma_tf32(float c[4], const uint32_t a[4], const uint32_t b[2]) {
    asm("mma.sync.aligned.m16n8k8.row.col.f32.tf32.tf32.f32 "
        "{%0,%1,%2,%3}, {%4,%5,%6,%7}, {%8,%9}, {%0,%1,%2,%3};"
        : "+f"(c[0]), "+f"(c[1]), "+f"(c[2]), "+f"(c[3])
        : "r"(a[0]), "r"(a[1]), "r"(a[2]), "r"(a[3]), "r"(b[0]), "r"(b[1]));
}

__global__ __launch_bounds__(128) void proj_kernel(
    const float* __restrict__ W, const float* __restrict__ bp,
    const float* __restrict__ x, float* __restrict__ out)
{
    __shared__ uint32_t As[2][PBK][PBM + PPAD];   // [k][m], tf32 bits
    __shared__ uint32_t Bs[2][PBK][PBN + PPAD];   // [k][n], tf32 bits

    const int b   = blockIdx.z;
    const int m0  = blockIdx.y * PBM;
    const int n0  = blockIdx.x * PBN;
    const int tid = threadIdx.x;
    const int wid  = tid >> 5;
    const int lane = tid & 31;
    const int g  = lane >> 2;        // group id 0..7
    const int tg = lane & 3;         // thread-in-group 0..3
    const int wm = (wid >> 1) * 32;  // warp m offset
    const int wn = (wid & 1) * 32;   // warp n offset

    const float* Ab = g_attn + (size_t)b * CH * TIME;

    float acc[2][4][4];
    #pragma unroll
    for (int i = 0; i < 2; i++)
        #pragma unroll
        for (int j = 0; j < 4; j++)
            #pragma unroll
            for (int r = 0; r < 4; r++) acc[i][j][r] = 0.f;

    auto stage = [&](int buf, int k0) {
        #pragma unroll
        for (int i = 0; i < 2; i++) {
            int id = tid + i * 128;              // 0..255
            // A: W[m0+row][k0+c4 .. +3] -> As[k][m]
            int row = id >> 2, c4 = (id & 3) * 4;
            float4 v = *reinterpret_cast<const float4*>(&W[(size_t)(m0 + row) * CH + k0 + c4]);
            As[buf][c4 + 0][row] = f2tf32(v.x);
            As[buf][c4 + 1][row] = f2tf32(v.y);
            As[buf][c4 + 2][row] = f2tf32(v.z);
            As[buf][c4 + 3][row] = f2tf32(v.w);
            // B: attn[k0+r][n0+n4 .. +3] -> Bs[k][n]
            int r = id >> 4, n4 = (id & 15) * 4;
            float4 u = *reinterpret_cast<const float4*>(&Ab[(size_t)(k0 + r) * TIME + n0 + n4]);
            uint4 tv;
            tv.x = f2tf32(u.x); tv.y = f2tf32(u.y);
            tv.z = f2tf32(u.z); tv.w = f2tf32(u.w);
            *reinterpret_cast<uint4*>(&Bs[buf][r][n4]) = tv;
        }
    };

    stage(0, 0);
    __syncthreads();

    for (int k0 = 0; k0 < CH; k0 += PBK) {
        const int buf = (k0 / PBK) & 1;
        if (k0 + PBK < CH) stage(buf ^ 1, k0 + PBK);

        #pragma unroll
        for (int kk = 0; kk < PBK; kk += 8) {
            uint32_t a[2][4], bf[4][2];
            #pragma unroll
            for (int fm = 0; fm < 2; fm++) {
                int mr = wm + fm * 16 + g;
                a[fm][0] = As[buf][kk + tg    ][mr];
                a[fm][1] = As[buf][kk + tg    ][mr + 8];
                a[fm][2] = As[buf][kk + tg + 4][mr];
                a[fm][3] = As[buf][kk + tg + 4][mr + 8];
            }
            #pragma unroll
            for (int fn = 0; fn < 4; fn++) {
                int nc = wn + fn * 8 + g;
                bf[fn][0] = Bs[buf][kk + tg    ][nc];
                bf[fn][1] = Bs[buf][kk + tg + 4][nc];
            }
            #pragma unroll
            for (int fm = 0; fm < 2; fm++)
                #pragma unroll
                for (int fn = 0; fn < 4; fn++)
                    mma_tf32(acc[fm][fn], a[fm], bf[fn]);
        }
        __syncthreads();
    }

    // ---- epilogue: bias + residual ----
    const float* xb = x + (size_t)b * CH * TIME;
    float*       ob = out + (size_t)b * CH * TIME;
    #pragma unroll
    for (int fm = 0; fm < 2; fm++) {
        int row0 = m0 + wm + fm * 16 + g;
        float bias0 = bp[row0];
        float bias1 = bp[row0 + 8];
        #pragma unroll
        for (int fn = 0; fn < 4; fn++) {
            int col = n0 + wn + fn * 8 + tg * 2;
            size_t off0 = (size_t)row0 * TIME + col;
            size_t off1 = (size_t)(row0 + 8) * TIME + col;
            float2 x0 = *reinterpret_cast<const float2*>(&xb[off0]);
            float2 x1 = *reinterpret_cast<const float2*>(&xb[off1]);
            float2 o0, o1;
            o0.x = x0.x + bias0 + acc[fm][fn][0];
            o0.y = x0.y + bias0 + acc[fm][fn][1];
            o1.x = x1.x + bias1 + acc[fm][fn][2];
            o1.y = x1.y + bias1 + acc[fm][fn][3];
            *reinterpret_cast<float2*>(&ob[off0]) = o0;
            *reinterpret_cast<float2*>(&ob[off1]) = o1;
        }
    }
}

// ---------------------------------------------------------------------------
extern "C" void kernel_launch(void* const* d_in, const int* in_sizes, int n_in,
                              void* d_out, int out_size) {
    const float* x  = (const float*)d_in[0];
    const float* wq = (const float*)d_in[1];
    const float* bq = (const float*)d_in[2];
    const float* wk = (const float*)d_in[3];
    const float* bk = (const float*)d_in[4];
    const float* wv = (const float*)d_in[5];
    const float* bv = (const float*)d_in[6];
    const float* wp = (const float*)d_in[7];
    const float* bp = (const float*)d_in[8];
    float* out = (float*)d_out;

    attn_kernel<<<BATCH * (TIME / TT), 256>>>(x, wq, bq, wk, bk, wv, bv);

    dim3 grid(TIME / PBN, CH / PBM, BATCH);
    proj_kernel<<<grid, 128>>>(wp, bp, x, out);
}

// round 8
// speedup vs baseline: 1.5589x; 1.0941x over previous
#include <cuda_runtime.h>
#include <cuda_bf16.h>
#include <cstdint>

#define BATCH 2
#define CH    512
#define TIME  2048
#define DIM   64
#define TT    4
#define EPS_F 1e-6f
#define L2E_F 1.44269504088896340736f
#define LN2_F 0.69314718055994530942f

// Attention output, bf16, TRANSPOSED layout [B][T][C] (c contiguous).
// This is exactly the col-major B-fragment layout proj needs.
__device__ __nv_bfloat16 g_attnT[BATCH * TIME * CH];

__device__ __forceinline__ float ex2f(float v) {
    float r;
    asm("ex2.approx.f32 %0, %1;" : "=f"(r) : "f"(v));
    return r;
}

// ---------------------------------------------------------------------------
// Kernel A: linear attention over channels. TT=4 t's per block, 256 threads.
// ---------------------------------------------------------------------------
__global__ __launch_bounds__(256) void attn_kernel(
    const float* __restrict__ x,
    const float* __restrict__ wq, const float* __restrict__ bq,
    const float* __restrict__ wk, const float* __restrict__ bk,
    const float* __restrict__ wv, const float* __restrict__ bv)
{
    __shared__ float  xs[TT][CH];     // 8 KB, t-major (broadcast reads)
    __shared__ float2 sz[TT][DIM];    // 2 KB  (S, clamped Z)
    __shared__ float2 wbq[DIM];       // pre-scaled (wq*log2e, bq*log2e)

    const int tile = blockIdx.x;                 // 1024 tiles
    const int b    = tile / (TIME / TT);
    const int t0   = (tile % (TIME / TT)) * TT;
    const int tid  = threadIdx.x;
    const int wid  = tid >> 5;
    const int lane = tid & 31;

    if (tid < DIM) wbq[tid] = make_float2(wq[tid] * L2E_F, bq[tid] * L2E_F);

    // Load x[b, :, t0:t0+4] -> xs[t][c]
    const float* xg = x + (size_t)b * CH * TIME + t0;
    for (int c = tid; c < CH; c += 256) {
        float4 v = *reinterpret_cast<const float4*>(&xg[(size_t)c * TIME]);
        xs[0][c] = v.x; xs[1][c] = v.y; xs[2][c] = v.z; xs[3][c] = v.w;
    }
    __syncthreads();

    const int t = wid >> 1;

    // ---- Phase 1: per (d,t): S = wv*sum(phi_k*x) + bv*Z ; Z = sum(phi_k) ----
    {
        const int d = (wid & 1) * 32 + lane;
        const float w2 = wk[d] * L2E_F, b2 = bk[d] * L2E_F;
        float SXa = 0.f, Za = 0.f, SXb = 0.f, Zb = 0.f;  // 2 chains for ILP
        const float* xrow = xs[t];
        #pragma unroll 2
        for (int c = 0; c < CH; c += 8) {
            float4 xA = *reinterpret_cast<const float4*>(&xrow[c]);      // broadcast
            float4 xB = *reinterpret_cast<const float4*>(&xrow[c + 4]);
            float va[4] = {xA.x, xA.y, xA.z, xA.w};
            float vb[4] = {xB.x, xB.y, xB.z, xB.w};
            #pragma unroll
            for (int r = 0; r < 4; r++) {
                float u = fmaf(va[r], w2, b2);
                float e = ex2f(fminf(u, 0.f));
                float p = fmaf(fmaxf(u, 0.f), LN2_F, e);
                SXa = fmaf(p, va[r], SXa); Za += p;
                float u2 = fmaf(vb[r], w2, b2);
                float e2 = ex2f(fminf(u2, 0.f));
                float p2 = fmaf(fmaxf(u2, 0.f), LN2_F, e2);
                SXb = fmaf(p2, vb[r], SXb); Zb += p2;
            }
        }
        float SX = SXa + SXb, Z = Za + Zb;
        const float wvv = __ldg(wv), bvv = __ldg(bv);
        sz[t][d] = make_float2(fmaf(wvv, SX, bvv * Z), fmaxf(Z, EPS_F));
    }
    __syncthreads();

    // ---- Phase 2: out[c,t] = sum_d(phi_q*S_d) / sum_d(phi_q*Z_d) ----
    {
        const int base = lane + (wid & 1) * 256;
        float xr[8], num[8], den[8];
        #pragma unroll
        for (int j = 0; j < 8; j++) {
            xr[j] = xs[t][base + 32 * j];
            num[j] = 0.f; den[j] = 0.f;
        }
        #pragma unroll 4
        for (int d = 0; d < DIM; d += 2) {
            float4 wb  = *reinterpret_cast<const float4*>(&wbq[d]);    // broadcast
            float4 szp = *reinterpret_cast<const float4*>(&sz[t][d]);  // broadcast
            #pragma unroll
            for (int j = 0; j < 8; j++) {
                float xv = xr[j];
                float u0 = fmaf(xv, wb.x, wb.y);
                float u1 = fmaf(xv, wb.z, wb.w);
                float e0 = ex2f(fminf(u0, 0.f));
                float e1 = ex2f(fminf(u1, 0.f));
                float p0 = fmaf(fmaxf(u0, 0.f), LN2_F, e0);
                float p1 = fmaf(fmaxf(u1, 0.f), LN2_F, e1);
                num[j] = fmaf(p0, szp.x, num[j]);
                den[j] = fmaf(p0, szp.y, den[j]);
                num[j] = fmaf(p1, szp.z, num[j]);
                den[j] = fmaf(p1, szp.w, den[j]);
            }
        }
        #pragma unroll
        for (int j = 0; j < 8; j++)
            xs[t][base + 32 * j] = num[j] / den[j];
    }
    __syncthreads();

    // Coalesced bf16 store: g_attnT[b][t0+t][c]  (c contiguous)
    __nv_bfloat162* op = reinterpret_cast<__nv_bfloat162*>(
        g_attnT + ((size_t)b * TIME + t0) * CH);
    for (int i = tid; i < TT * (CH / 2); i += 256) {
        int tt = i / (CH / 2);
        int cp = i % (CH / 2);
        op[(size_t)tt * (CH / 2) + cp] =
            __floats2bfloat162_rn(xs[tt][2 * cp], xs[tt][2 * cp + 1]);
    }
}

// ---------------------------------------------------------------------------
// Kernel B: out[b,o,t] = x[b,o,t] + b_proj[o] + sum_c W[o,c]*attn[b,c,t]
// bf16 mma m16n8k16 + ldmatrix. 64x64x32 CTA tile double-buffered,
// 256 threads = 8 warps in 2(m) x 4(n), warp tile 32x16.
// ---------------------------------------------------------------------------
#define PBM 64
#define PBN 64
#define PBK 32
#define KPAD 8   // row stride 40 halves = 20 words -> conflict-free ldmatrix

__device__ __forceinline__ void ldsm_x4(uint32_t r[4], uint32_t addr) {
    asm volatile("ldmatrix.sync.aligned.m8n8.x4.shared.b16 {%0,%1,%2,%3}, [%4];"
                 : "=r"(r[0]), "=r"(r[1]), "=r"(r[2]), "=r"(r[3]) : "r"(addr));
}
__device__ __forceinline__ void ldsm_x2(uint32_t r[2], uint32_t addr) {
    asm volatile("ldmatrix.sync.aligned.m8n8.x2.shared.b16 {%0,%1}, [%2];"
                 : "=r"(r[0]), "=r"(r[1]) : "r"(addr));
}
__device__ __forceinline__ void mma_bf16(float c[4], const uint32_t a[4], const uint32_t b[2]) {
    asm("mma.sync.aligned.m16n8k16.row.col.f32.bf16.bf16.f32 "
        "{%0,%1,%2,%3}, {%4,%5,%6,%7}, {%8,%9}, {%0,%1,%2,%3};"
        : "+f"(c[0]), "+f"(c[1]), "+f"(c[2]), "+f"(c[3])
        : "r"(a[0]), "r"(a[1]), "r"(a[2]), "r"(a[3]), "r"(b[0]), "r"(b[1]));
}

__global__ __launch_bounds__(256) void proj_kernel(
    const float* __restrict__ W, const float* __restrict__ bp,
    const float* __restrict__ x, float* __restrict__ out)
{
    __shared__ __nv_bfloat16 As[2][PBM][PBK + KPAD];   // [m][k]
    __shared__ __nv_bfloat16 Bs[2][PBN][PBK + KPAD];   // [n][k]

    const int b   = blockIdx.z;
    const int m0  = blockIdx.y * PBM;
    const int n0  = blockIdx.x * PBN;
    const int tid = threadIdx.x;
    const int wid  = tid >> 5;
    const int lane = tid & 31;
    const int g  = lane >> 2;        // 0..7
    const int tg = lane & 3;         // 0..3
    const int wm = (wid >> 2) * 32;  // {0,32}
    const int wn = (wid & 3) * 16;   // {0,16,32,48}

    const __nv_bfloat16* Bg = g_attnT + (size_t)b * TIME * CH;

    const uint32_t as_base = (uint32_t)__cvta_generic_to_shared(&As[0][0][0]);
    const uint32_t bs_base = (uint32_t)__cvta_generic_to_shared(&Bs[0][0][0]);
    const uint32_t buf_stride = PBM * (PBK + KPAD) * 2;  // bytes per buffer

    // staging indices: 256 threads, 64 rows x 32 k, 8 k per thread
    const int srow = tid >> 2;
    const int skq  = (tid & 3) * 8;

    float acc[2][2][4];
    #pragma unroll
    for (int i = 0; i < 2; i++)
        #pragma unroll
        for (int j = 0; j < 2; j++)
            #pragma unroll
            for (int r = 0; r < 4; r++) acc[i][j][r] = 0.f;

    auto stage = [&](int buf, int k0) {
        // A: W[m0+srow][k0+skq .. +7] fp32 -> bf16
        const float* wp4 = &W[(size_t)(m0 + srow) * CH + k0 + skq];
        float4 v0 = *reinterpret_cast<const float4*>(wp4);
        float4 v1 = *reinterpret_cast<const float4*>(wp4 + 4);
        __nv_bfloat162 h[4];
        h[0] = __floats2bfloat162_rn(v0.x, v0.y);
        h[1] = __floats2bfloat162_rn(v0.z, v0.w);
        h[2] = __floats2bfloat162_rn(v1.x, v1.y);
        h[3] = __floats2bfloat162_rn(v1.z, v1.w);
        *reinterpret_cast<uint4*>(&As[buf][srow][skq]) = *reinterpret_cast<uint4*>(h);
        // B: g_attnT[n0+srow][k0+skq .. +7] raw bf16 copy
        uint4 u = *reinterpret_cast<const uint4*>(&Bg[(size_t)(n0 + srow) * CH + k0 + skq]);
        *reinterpret_cast<uint4*>(&Bs[buf][srow][skq]) = u;
    };

    stage(0, 0);
    __syncthreads();

    // precomputed ldmatrix lane addressing
    const int a_row = wm + (lane & 15);
    const int a_k   = ((lane >> 4) & 1) * 8;
    const int b_row = wn + (lane & 7);
    const int b_k   = ((lane >> 3) & 1) * 8;

    for (int k0 = 0; k0 < CH; k0 += PBK) {
        const int buf = (k0 / PBK) & 1;
        if (k0 + PBK < CH) stage(buf ^ 1, k0 + PBK);

        const uint32_t ab = as_base + buf * buf_stride;
        const uint32_t bb = bs_base + buf * buf_stride;

        #pragma unroll
        for (int kk = 0; kk < PBK; kk += 16) {
            uint32_t a[2][4], bf[2][2];
            #pragma unroll
            for (int fm = 0; fm < 2; fm++)
                ldsm_x4(a[fm], ab + ((a_row + fm * 16) * (PBK + KPAD) + kk + a_k) * 2);
            #pragma unroll
            for (int fn = 0; fn < 2; fn++)
                ldsm_x2(bf[fn], bb + ((b_row + fn * 8) * (PBK + KPAD) + kk + b_k) * 2);
            #pragma unroll
            for (int fm = 0; fm < 2; fm++)
                #pragma unroll
                for (int fn = 0; fn < 2; fn++)
                    mma_bf16(acc[fm][fn], a[fm], bf[fn]);
        }
        __syncthreads();
    }

    // ---- epilogue: bias + residual ----
    const float* xb = x + (size_t)b * CH * TIME;
    float*       ob = out + (size_t)b * CH * TIME;
    #pragma unroll
    for (int fm = 0; fm < 2; fm++) {
        int row0 = m0 + wm + fm * 16 + g;
        float bias0 = bp[row0];
        float bias1 = bp[row0 + 8];
        #pragma unroll
        for (int fn = 0; fn < 2; fn++) {
            int col = n0 + wn + fn * 8 + tg * 2;
            size_t off0 = (size_t)row0 * TIME + col;
            size_t off1 = (size_t)(row0 + 8) * TIME + col;
            float2 x0 = *reinterpret_cast<const float2*>(&xb[off0]);
            float2 x1 = *reinterpret_cast<const float2*>(&xb[off1]);
            float2 o0, o1;
            o0.x = x0.x + bias0 + acc[fm][fn][0];
            o0.y = x0.y + bias0 + acc[fm][fn][1];
            o1.x = x1.x + bias1 + acc[fm][fn][2];
            o1.y = x1.y + bias1 + acc[fm][fn][3];
            *reinterpret_cast<float2*>(&ob[off0]) = o0;
            *reinterpret_cast<float2*>(&ob[off1]) = o1;
        }
    }
}

// ---------------------------------------------------------------------------
extern "C" void kernel_launch(void* const* d_in, const int* in_sizes, int n_in,
                              void* d_out, int out_size) {
    const float* x  = (const float*)d_in[0];
    const float* wq = (const float*)d_in[1];
    const float* bq = (const float*)d_in[2];
    const float* wk = (const float*)d_in[3];
    const float* bk = (const float*)d_in[4];
    const float* wv = (const float*)d_in[5];
    const float* bv = (const float*)d_in[6];
    const float* wp = (const float*)d_in[7];
    const float* bp = (const float*)d_in[8];
    float* out = (float*)d_out;

    attn_kernel<<<BATCH * (TIME / TT), 256>>>(x, wq, bq, wk, bk, wv, bv);

    dim3 grid(TIME / PBN, CH / PBM, BATCH);
    proj_kernel<<<grid, 256>>>(wp, bp, x, out);
}

// round 9
// speedup vs baseline: 1.7716x; 1.1364x over previous
#include <cuda_runtime.h>
#include <cuda_bf16.h>
#include <cstdint>

#define BATCH 2
#define CH    512
#define TIME  2048
#define DIM   64
#define TT    4
#define EPS_F 1e-6f
#define L2E_F 1.44269504088896340736f
#define LN2_F 0.69314718055994530942f

typedef unsigned long long ull;

// Attention output, bf16, TRANSPOSED layout [B][T][C] (c contiguous).
__device__ __nv_bfloat16 g_attnT[BATCH * TIME * CH];
// W pre-converted to bf16 (filled by attn_kernel's prologue).
__device__ __nv_bfloat16 g_Wbf[CH * CH];

__device__ __forceinline__ float ex2f(float v) {
    float r;
    asm("ex2.approx.f32 %0, %1;" : "=f"(r) : "f"(v));
    return r;
}
__device__ __forceinline__ ull pk2(float lo, float hi) {
    ull r; asm("mov.b64 %0, {%1, %2};" : "=l"(r) : "f"(lo), "f"(hi)); return r;
}
__device__ __forceinline__ void upk2(ull v, float& lo, float& hi) {
    asm("mov.b64 {%0, %1}, %2;" : "=f"(lo), "=f"(hi) : "l"(v));
}
__device__ __forceinline__ ull fma2_(ull a, ull b, ull c) {
    ull r; asm("fma.rn.f32x2 %0, %1, %2, %3;" : "=l"(r) : "l"(a), "l"(b), "l"(c)); return r;
}
__device__ __forceinline__ ull add2_(ull a, ull b) {
    ull r; asm("add.rn.f32x2 %0, %1, %2;" : "=l"(r) : "l"(a), "l"(b)); return r;
}

// ---------------------------------------------------------------------------
// Kernel A: linear attention over channels. TT=4 t's per block, 256 threads.
// Packed f32x2 math: MUFU (ex2) is the sole binding pipe (~8 cyc/phi).
// ---------------------------------------------------------------------------
__global__ __launch_bounds__(256) void attn_kernel(
    const float* __restrict__ x,
    const float* __restrict__ wq, const float* __restrict__ bq,
    const float* __restrict__ wk, const float* __restrict__ bk,
    const float* __restrict__ wv, const float* __restrict__ bv,
    const float* __restrict__ W)
{
    __shared__ float  xs[TT][CH];     // 8 KB, t-major (broadcast reads)
    __shared__ float2 sz[TT][DIM];    // 2 KB  (S, clamped Z)
    __shared__ float2 wbq[DIM];       // pre-scaled (wq*log2e, bq*log2e)

    const int tile = blockIdx.x;                 // 1024 tiles
    const int b    = tile / (TIME / TT);
    const int t0   = (tile % (TIME / TT)) * TT;
    const int tid  = threadIdx.x;
    const int wid  = tid >> 5;
    const int lane = tid & 31;

    // Prologue: convert this block's slice of W to bf16 (1024*256 == 512*512)
    {
        int wi = tile * 256 + tid;
        g_Wbf[wi] = __float2bfloat16_rn(W[wi]);
    }

    if (tid < DIM) wbq[tid] = make_float2(wq[tid] * L2E_F, bq[tid] * L2E_F);

    // Load x[b, :, t0:t0+4] -> xs[t][c]
    const float* xg = x + (size_t)b * CH * TIME + t0;
    for (int c = tid; c < CH; c += 256) {
        float4 v = *reinterpret_cast<const float4*>(&xg[(size_t)c * TIME]);
        xs[0][c] = v.x; xs[1][c] = v.y; xs[2][c] = v.z; xs[3][c] = v.w;
    }
    __syncthreads();

    const int t = wid >> 1;
    const ull ln2p = pk2(LN2_F, LN2_F);

    // ---- Phase 1: per (d,t): S = wv*sum(phi_k*x) + bv*Z ; Z = sum(phi_k) ----
    {
        const int d = (wid & 1) * 32 + lane;
        const float w2 = wk[d] * L2E_F, b2 = bk[d] * L2E_F;
        const ull w2p = pk2(w2, w2), b2p = pk2(b2, b2);
        ull SX2 = pk2(0.f, 0.f), Z2 = pk2(0.f, 0.f);
        const float* xrow = xs[t];
        #pragma unroll 4
        for (int c = 0; c < CH; c += 4) {
            float4 x4 = *reinterpret_cast<const float4*>(&xrow[c]);  // broadcast
            {
                ull xp = pk2(x4.x, x4.y);
                ull u  = fma2_(xp, w2p, b2p);
                float u0, u1; upk2(u, u0, u1);
                float e0 = ex2f(fminf(u0, 0.f));
                float e1 = ex2f(fminf(u1, 0.f));
                ull pp = fma2_(pk2(fmaxf(u0, 0.f), fmaxf(u1, 0.f)), ln2p, pk2(e0, e1));
                SX2 = fma2_(pp, xp, SX2);
                Z2  = add2_(Z2, pp);
            }
            {
                ull xp = pk2(x4.z, x4.w);
                ull u  = fma2_(xp, w2p, b2p);
                float u0, u1; upk2(u, u0, u1);
                float e0 = ex2f(fminf(u0, 0.f));
                float e1 = ex2f(fminf(u1, 0.f));
                ull pp = fma2_(pk2(fmaxf(u0, 0.f), fmaxf(u1, 0.f)), ln2p, pk2(e0, e1));
                SX2 = fma2_(pp, xp, SX2);
                Z2  = add2_(Z2, pp);
            }
        }
        float sxa, sxb, za, zb;
        upk2(SX2, sxa, sxb); upk2(Z2, za, zb);
        float SX = sxa + sxb, Z = za + zb;
        const float wvv = __ldg(wv), bvv = __ldg(bv);
        sz[t][d] = make_float2(fmaf(wvv, SX, bvv * Z), fmaxf(Z, EPS_F));
    }
    __syncthreads();

    // ---- Phase 2: out[c,t] = sum_d(phi_q*S_d) / sum_d(phi_q*Z_d) ----
    {
        const int base = lane + (wid & 1) * 256;
        ull xp2[4], num2[4], den2[4];
        float xr[8];
        #pragma unroll
        for (int j = 0; j < 8; j++) xr[j] = xs[t][base + 32 * j];
        #pragma unroll
        for (int jp = 0; jp < 4; jp++) {
            xp2[jp]  = pk2(xr[2 * jp], xr[2 * jp + 1]);
            num2[jp] = pk2(0.f, 0.f);
            den2[jp] = pk2(0.f, 0.f);
        }
        #pragma unroll 2
        for (int d = 0; d < DIM; d++) {
            float2 wb  = wbq[d];       // broadcast
            float2 szv = sz[t][d];     // broadcast
            ull wp = pk2(wb.x, wb.x), bp2 = pk2(wb.y, wb.y);
            ull Sp = pk2(szv.x, szv.x), Zp = pk2(szv.y, szv.y);
            #pragma unroll
            for (int jp = 0; jp < 4; jp++) {
                ull u = fma2_(xp2[jp], wp, bp2);
                float u0, u1; upk2(u, u0, u1);
                float e0 = ex2f(fminf(u0, 0.f));
                float e1 = ex2f(fminf(u1, 0.f));
                ull pp = fma2_(pk2(fmaxf(u0, 0.f), fmaxf(u1, 0.f)), ln2p, pk2(e0, e1));
                num2[jp] = fma2_(pp, Sp, num2[jp]);
                den2[jp] = fma2_(pp, Zp, den2[jp]);
            }
        }
        #pragma unroll
        for (int jp = 0; jp < 4; jp++) {
            float n0, n1, d0, d1;
            upk2(num2[jp], n0, n1); upk2(den2[jp], d0, d1);
            xs[t][base + 32 * (2 * jp)]     = __fdividef(n0, d0);
            xs[t][base + 32 * (2 * jp + 1)] = __fdividef(n1, d1);
        }
    }
    __syncthreads();

    // Coalesced bf16 store: g_attnT[b][t0+t][c]  (c contiguous)
    __nv_bfloat162* op = reinterpret_cast<__nv_bfloat162*>(
        g_attnT + ((size_t)b * TIME + t0) * CH);
    for (int i = tid; i < TT * (CH / 2); i += 256) {
        int tt = i / (CH / 2);
        int cp = i % (CH / 2);
        op[(size_t)tt * (CH / 2) + cp] =
            __floats2bfloat162_rn(xs[tt][2 * cp], xs[tt][2 * cp + 1]);
    }
}

// ---------------------------------------------------------------------------
// Kernel B: out[b,o,t] = x[b,o,t] + b_proj[o] + sum_c W[o,c]*attn[b,c,t]
// bf16 mma m16n8k16 + ldmatrix.x4 + cp.async double buffering.
// 64x64x64 CTA tile, 128 threads = 4 warps (2x2), warp tile 32x32.
// ---------------------------------------------------------------------------
#define PBM 64
#define PBN 64
#define PBK 64
#define KST (PBK + 8)    // row stride 72 halves = 144B (16B-aligned, LDSM conflict-free)

__device__ __forceinline__ void cp16(uint32_t dst, const void* src) {
    asm volatile("cp.async.cg.shared.global [%0], [%1], 16;" :: "r"(dst), "l"(src));
}
__device__ __forceinline__ void ldsm_x4(uint32_t r[4], uint32_t addr) {
    asm volatile("ldmatrix.sync.aligned.m8n8.x4.shared.b16 {%0,%1,%2,%3}, [%4];"
                 : "=r"(r[0]), "=r"(r[1]), "=r"(r[2]), "=r"(r[3]) : "r"(addr));
}
__device__ __forceinline__ void mma_bf16(float c[4], const uint32_t a[4], const uint32_t b0, const uint32_t b1) {
    asm("mma.sync.aligned.m16n8k16.row.col.f32.bf16.bf16.f32 "
        "{%0,%1,%2,%3}, {%4,%5,%6,%7}, {%8,%9}, {%0,%1,%2,%3};"
        : "+f"(c[0]), "+f"(c[1]), "+f"(c[2]), "+f"(c[3])
        : "r"(a[0]), "r"(a[1]), "r"(a[2]), "r"(a[3]), "r"(b0), "r"(b1));
}

__global__ __launch_bounds__(128) void proj_kernel(
    const float* __restrict__ bp,
    const float* __restrict__ x, float* __restrict__ out)
{
    __shared__ __nv_bfloat16 As[2][PBM][KST];   // [m][k]  9216 B/buf
    __shared__ __nv_bfloat16 Bs[2][PBN][KST];   // [n][k]

    const int b   = blockIdx.z;
    const int m0  = blockIdx.y * PBM;
    const int n0  = blockIdx.x * PBN;
    const int tid = threadIdx.x;
    const int wid  = tid >> 5;
    const int lane = tid & 31;
    const int g  = lane >> 2;        // 0..7
    const int tg = lane & 3;         // 0..3
    const int wm = (wid >> 1) * 32;  // {0,32}
    const int wn = (wid & 1) * 32;   // {0,32}

    const __nv_bfloat16* Bg = g_attnT + (size_t)b * TIME * CH;

    // staging: 128 threads, 64 rows x 64 k; thread -> row=tid>>1, k-half=(tid&1)*32
    const int srow = tid >> 1;
    const int skb  = (tid & 1) * 32;

    float acc[2][4][4];
    #pragma unroll
    for (int i = 0; i < 2; i++)
        #pragma unroll
        for (int j = 0; j < 4; j++)
            #pragma unroll
            for (int r = 0; r < 4; r++) acc[i][j][r] = 0.f;

    auto stage = [&](int buf, int k0) {
        const __nv_bfloat16* sA = &g_Wbf[(size_t)(m0 + srow) * CH + k0 + skb];
        const __nv_bfloat16* sB = &Bg[(size_t)(n0 + srow) * CH + k0 + skb];
        uint32_t da = (uint32_t)__cvta_generic_to_shared(&As[buf][srow][skb]);
        uint32_t db = (uint32_t)__cvta_generic_to_shared(&Bs[buf][srow][skb]);
        #pragma unroll
        for (int i = 0; i < 4; i++) {
            cp16(da + i * 16, sA + i * 8);
            cp16(db + i * 16, sB + i * 8);
        }
    };

    stage(0, 0);
    asm volatile("cp.async.commit_group;");

    // ldmatrix lane addressing
    const int a_row = wm + (lane & 15);
    const int a_k   = ((lane >> 4) & 1) * 8;
    const int b_row = wn + (lane & 7) + ((lane >> 4) & 1) * 8;
    const int b_k   = ((lane >> 3) & 1) * 8;

    const int NIT = CH / PBK;   // 8
    for (int it = 0; it < NIT; it++) {
        if (it + 1 < NIT) {
            stage((it + 1) & 1, (it + 1) * PBK);
            asm volatile("cp.async.commit_group;");
            asm volatile("cp.async.wait_group 1;");
        } else {
            asm volatile("cp.async.wait_group 0;");
        }
        __syncthreads();

        const int buf = it & 1;
        const uint32_t ab = (uint32_t)__cvta_generic_to_shared(&As[buf][0][0]);
        const uint32_t bb = (uint32_t)__cvta_generic_to_shared(&Bs[buf][0][0]);

        #pragma unroll
        for (int kk = 0; kk < PBK; kk += 16) {
            uint32_t a[2][4], bf[2][4];
            #pragma unroll
            for (int fm = 0; fm < 2; fm++)
                ldsm_x4(a[fm], ab + ((a_row + fm * 16) * KST + kk + a_k) * 2);
            #pragma unroll
            for (int bh = 0; bh < 2; bh++)
                ldsm_x4(bf[bh], bb + ((b_row + bh * 16) * KST + kk + b_k) * 2);
            #pragma unroll
            for (int fm = 0; fm < 2; fm++)
                #pragma unroll
                for (int bh = 0; bh < 2; bh++) {
                    mma_bf16(acc[fm][bh * 2 + 0], a[fm], bf[bh][0], bf[bh][1]);
                    mma_bf16(acc[fm][bh * 2 + 1], a[fm], bf[bh][2], bf[bh][3]);
                }
        }
        __syncthreads();
    }

    // ---- epilogue: bias + residual ----
    const float* xb = x + (size_t)b * CH * TIME;
    float*       ob = out + (size_t)b * CH * TIME;
    #pragma unroll
    for (int fm = 0; fm < 2; fm++) {
        int row0 = m0 + wm + fm * 16 + g;
        float bias0 = bp[row0];
        float bias1 = bp[row0 + 8];
        #pragma unroll
        for (int fn = 0; fn < 4; fn++) {
            int col = n0 + wn + fn * 8 + tg * 2;
            size_t off0 = (size_t)row0 * TIME + col;
            size_t off1 = (size_t)(row0 + 8) * TIME + col;
            float2 x0 = *reinterpret_cast<const float2*>(&xb[off0]);
            float2 x1 = *reinterpret_cast<const float2*>(&xb[off1]);
            float2 o0, o1;
            o0.x = x0.x + bias0 + acc[fm][fn][0];
            o0.y = x0.y + bias0 + acc[fm][fn][1];
            o1.x = x1.x + bias1 + acc[fm][fn][2];
            o1.y = x1.y + bias1 + acc[fm][fn][3];
            *reinterpret_cast<float2*>(&ob[off0]) = o0;
            *reinterpret_cast<float2*>(&ob[off1]) = o1;
        }
    }
}

// ---------------------------------------------------------------------------
extern "C" void kernel_launch(void* const* d_in, const int* in_sizes, int n_in,
                              void* d_out, int out_size) {
    const float* x  = (const float*)d_in[0];
    const float* wq = (const float*)d_in[1];
    const float* bq = (const float*)d_in[2];
    const float* wk = (const float*)d_in[3];
    const float* bk = (const float*)d_in[4];
    const float* wv = (const float*)d_in[5];
    const float* bv = (const float*)d_in[6];
    const float* wp = (const float*)d_in[7];
    const float* bp = (const float*)d_in[8];
    float* out = (float*)d_out;

    attn_kernel<<<BATCH * (TIME / TT), 256>>>(x, wq, bq, wk, bk, wv, bv, wp);

    dim3 grid(TIME / PBN, CH / PBM, BATCH);
    proj_kernel<<<grid, 128>>>(bp, x, out);
}